// round 13
// baseline (speedup 1.0000x reference)
#include <cuda_runtime.h>
#include <math.h>
#include <stdint.h>

#define B_  2
#define S_  2048
#define D_  1024
#define H_  16
#define HD_ 64
#define M_  (B_ * S_)    // 4096
#define N3_ (3 * D_)     // 3072

// Scratch for Q/K/V in (b*H+h, s, e) layout. All tf32-rounded.
__device__ float g_Q[(size_t)M_ * D_];      // tf32-rounded, pre-scaled by QSCALE
__device__ float g_K[(size_t)M_ * D_];      // tf32-rounded
__device__ float g_V[(size_t)M_ * D_];      // tf32-rounded

// ---------------------------------------------------------------------------
// TF32 / async helpers
// ---------------------------------------------------------------------------
__device__ __forceinline__ uint32_t f2tf(float x) {
    uint32_t r;
    asm("cvt.rna.tf32.f32 %0, %1;" : "=r"(r) : "f"(x));
    return r;
}
__device__ __forceinline__ float tf32r(float x) {
    uint32_t r;
    asm("cvt.rna.tf32.f32 %0, %1;" : "=r"(r) : "f"(x));
    return __uint_as_float(r);
}
__device__ __forceinline__ float ex2(float x) {
    float r;
    asm("ex2.approx.f32 %0, %1;" : "=f"(r) : "f"(x));
    return r;
}
__device__ __forceinline__ void mma_tf32(float c[4],
    uint32_t a0, uint32_t a1, uint32_t a2, uint32_t a3,
    uint32_t b0, uint32_t b1)
{
    asm volatile(
        "mma.sync.aligned.m16n8k8.row.col.f32.tf32.tf32.f32 "
        "{%0,%1,%2,%3}, {%4,%5,%6,%7}, {%8,%9}, {%0,%1,%2,%3};"
        : "+f"(c[0]), "+f"(c[1]), "+f"(c[2]), "+f"(c[3])
        : "r"(a0), "r"(a1), "r"(a2), "r"(a3), "r"(b0), "r"(b1));
}
__device__ __forceinline__ void cp_async16(uint32_t smem_addr, const void* gptr) {
    asm volatile("cp.async.cg.shared.global [%0], [%1], 16;"
                 :: "r"(smem_addr), "l"(gptr));
}
#define CP_COMMIT() asm volatile("cp.async.commit_group;" ::: "memory")
#define CP_WAIT(n)  asm volatile("cp.async.wait_group %0;" :: "n"(n) : "memory")

// Q scale: 1/sqrt(64) * log2(e) -> scores in log2 domain, softmax via ex2
#define QSCALE 0.1803368801111204f

// ---------------------------------------------------------------------------
// Kernel 1: QKV projection, single-pass TF32 MMA (UNCHANGED from R12).
// BM=128, BN=128, BK=16, 256 threads, warps 4(M)x2(N), warp tile 32x64.
// ---------------------------------------------------------------------------
#define GP_A 20
#define GP_W 136

__global__ __launch_bounds__(256, 2) void qkv_mma_kernel(
    const float* __restrict__ A, const float* __restrict__ W,
    const float* __restrict__ qbias, const float* __restrict__ vbias)
{
    __shared__ float Ahi[128 * GP_A];   // 10240 B
    __shared__ float Whi[16 * GP_W];    // 8704 B

    const int tid  = threadIdx.x;
    const int warp = tid >> 5;
    const int lane = tid & 31;
    const int g    = lane >> 2;
    const int t    = lane & 3;
    const int bm   = blockIdx.y * 128;
    const int bn   = blockIdx.x * 128;
    const int warpM = (warp >> 1) * 32;
    const int warpN = (warp & 1) * 64;

    float C[2][8][4];
    #pragma unroll
    for (int mf = 0; mf < 2; mf++)
        #pragma unroll
        for (int nf = 0; nf < 8; nf++)
            #pragma unroll
            for (int j = 0; j < 4; j++) C[mf][nf][j] = 0.f;

    int arow[2], acg[2], wkk[2], wnn[2];
    float4 pa[2], pw[2];
    #pragma unroll
    for (int i = 0; i < 2; i++) {
        int idx = tid + i * 256;
        arow[i] = idx >> 2;
        acg[i]  = (idx & 3) << 2;
        wkk[i]  = idx >> 5;
        wnn[i]  = (idx & 31) << 2;
        pa[i] = *(const float4*)(A + (size_t)(bm + arow[i]) * D_ + acg[i]);
        pw[i] = *(const float4*)(W + (size_t)wkk[i] * N3_ + bn + wnn[i]);
    }

    for (int k0 = 0; k0 < D_ / 16; k0++) {
        __syncthreads();

        #pragma unroll
        for (int i = 0; i < 2; i++) {
            float4 x = pa[i];
            *(float4*)&Ahi[arow[i] * GP_A + acg[i]] =
                make_float4(tf32r(x.x), tf32r(x.y), tf32r(x.z), tf32r(x.w));
            float4 y = pw[i];
            *(float4*)&Whi[wkk[i] * GP_W + wnn[i]] =
                make_float4(tf32r(y.x), tf32r(y.y), tf32r(y.z), tf32r(y.w));
        }
        __syncthreads();

        if (k0 < D_ / 16 - 1) {
            #pragma unroll
            for (int i = 0; i < 2; i++) {
                pa[i] = *(const float4*)(A + (size_t)(bm + arow[i]) * D_
                                           + (k0 + 1) * 16 + acg[i]);
                pw[i] = *(const float4*)(W + (size_t)((k0 + 1) * 16 + wkk[i]) * N3_
                                           + bn + wnn[i]);
            }
        }

        #pragma unroll
        for (int kc = 0; kc < 2; kc++) {
            uint32_t ah[2][4];
            #pragma unroll
            for (int mf = 0; mf < 2; mf++) {
                int r0 = (warpM + mf * 16 + g) * GP_A + kc * 8 + t;
                ah[mf][0] = __float_as_uint(Ahi[r0]);
                ah[mf][1] = __float_as_uint(Ahi[r0 + 8 * GP_A]);
                ah[mf][2] = __float_as_uint(Ahi[r0 + 4]);
                ah[mf][3] = __float_as_uint(Ahi[r0 + 8 * GP_A + 4]);
            }
            #pragma unroll
            for (int nf = 0; nf < 8; nf++) {
                int n  = warpN + nf * 8 + g;
                int kb = (kc * 8 + t) * GP_W + n;
                uint32_t bh0 = __float_as_uint(Whi[kb]);
                uint32_t bh1 = __float_as_uint(Whi[kb + 4 * GP_W]);
                #pragma unroll
                for (int mf = 0; mf < 2; mf++)
                    mma_tf32(C[mf][nf], ah[mf][0], ah[mf][1], ah[mf][2], ah[mf][3], bh0, bh1);
            }
        }
    }

    const int which = bn >> 10;
    #pragma unroll
    for (int mf = 0; mf < 2; mf++) {
        int mrow = bm + warpM + mf * 16 + g;
        int b = mrow >> 11;
        int s = mrow & (S_ - 1);
        #pragma unroll
        for (int nf = 0; nf < 8; nf++) {
            int ncol = bn + warpN + nf * 8 + 2 * t;
            int d = ncol & (D_ - 1);
            int h = d >> 6;
            int e = d & 63;
            size_t i0 = ((size_t)(b * H_ + h) * S_ + s) * HD_ + e;
            size_t i1 = i0 + 8 * HD_;
            float c0 = C[mf][nf][0], c1 = C[mf][nf][1];
            float c2 = C[mf][nf][2], c3 = C[mf][nf][3];
            if (which == 0) {
                float b0 = qbias[d], b1 = qbias[d + 1];
                *(float2*)&g_Q[i0] = make_float2(tf32r((c0 + b0) * QSCALE),
                                                 tf32r((c1 + b1) * QSCALE));
                *(float2*)&g_Q[i1] = make_float2(tf32r((c2 + b0) * QSCALE),
                                                 tf32r((c3 + b1) * QSCALE));
            } else if (which == 1) {
                *(float2*)&g_K[i0] = make_float2(tf32r(c0), tf32r(c1));
                *(float2*)&g_K[i1] = make_float2(tf32r(c2), tf32r(c3));
            } else {
                float b0 = vbias[d], b1 = vbias[d + 1];
                *(float2*)&g_V[i0] = make_float2(tf32r(c0 + b0), tf32r(c1 + b1));
                *(float2*)&g_V[i1] = make_float2(tf32r(c2 + b0), tf32r(c3 + b1));
            }
        }
    }
}

// ---------------------------------------------------------------------------
// Kernel 2: flash attention, single-MMA QK/PV, DOUBLE-BUFFERED cp.async K/V
// staging (tile kt+1 copies overlap tile kt compute; L2 latency hidden).
// Block = 128 threads (4 warps), warp tile M=32, Br=128, Bc=64.
// smem: Qs [128][68] + 2x Khi [64][68] + 2x Vt [64][72] = 106496 B -> 2 blk/SM.
// Compute math identical to R12 attn7 (rel_err must be bit-identical).
// ---------------------------------------------------------------------------
#define QP 68
#define KP 68
#define VP 72
#define SM_Q (128 * QP)
#define SM_K (64 * KP)
#define SM_V (64 * VP)
#define ATTN_SMEM_BYTES ((SM_Q + 2 * SM_K + 2 * SM_V) * (int)sizeof(float)) // 106496

__global__ __launch_bounds__(128, 2) void attn8_kernel(float* __restrict__ out)
{
    extern __shared__ float sm[];
    float* Qs = sm;                                // [128][QP]
    float* Kb[2] = { sm + SM_Q, sm + SM_Q + SM_K };
    float* Vb[2] = { sm + SM_Q + 2 * SM_K, sm + SM_Q + 2 * SM_K + SM_V };

    const uint32_t smem_u32 = (uint32_t)__cvta_generic_to_shared(sm);
    const uint32_t q_u32  = smem_u32;
    const uint32_t k_u32[2] = { smem_u32 + SM_Q * 4u,
                                smem_u32 + (SM_Q + SM_K) * 4u };
    const uint32_t v_u32[2] = { smem_u32 + (SM_Q + 2 * SM_K) * 4u,
                                smem_u32 + (SM_Q + 2 * SM_K + SM_V) * 4u };

    const int tid  = threadIdx.x;
    const int warp = tid >> 5;
    const int lane = tid & 31;
    const int g    = lane >> 2;
    const int t    = lane & 3;
    const int wm   = warp * 32;
    const int bh   = blockIdx.y;
    const int qt   = blockIdx.x;

    const float* Qg = g_Q + ((size_t)bh * S_ + qt * 128) * HD_;
    const float* Kg = g_K + (size_t)bh * S_ * HD_;
    const float* Vg = g_V + (size_t)bh * S_ * HD_;

    // copy coordinates shared by Q/K/V staging
    const int crow = tid >> 4;           // 0..7  (+i*8)
    const int ccol = (tid & 15) << 2;    // 0,4,...,60

    // ---- prologue: Q tile (16 chunks/thread) + K/V tile 0, one group ----
    #pragma unroll
    for (int i = 0; i < 16; i++) {
        int row = crow + i * 8;
        cp_async16(q_u32 + (uint32_t)(row * QP + ccol) * 4u, Qg + row * HD_ + ccol);
    }
    #pragma unroll
    for (int i = 0; i < 8; i++) {
        int row = crow + i * 8;
        cp_async16(k_u32[0] + (uint32_t)(row * KP + ccol) * 4u, Kg + row * HD_ + ccol);
        cp_async16(v_u32[0] + (uint32_t)(row * VP + ccol) * 4u, Vg + row * HD_ + ccol);
    }
    CP_COMMIT();

    float m[2][2], l[2][2];
    #pragma unroll
    for (int mf = 0; mf < 2; mf++) {
        m[mf][0] = -INFINITY; m[mf][1] = -INFINITY;
        l[mf][0] = 0.f;       l[mf][1] = 0.f;
    }
    float O[2][8][4];
    #pragma unroll
    for (int mf = 0; mf < 2; mf++)
        #pragma unroll
        for (int nt = 0; nt < 8; nt++)
            #pragma unroll
            for (int j = 0; j < 4; j++) O[mf][nt][j] = 0.f;

    const int NT = S_ / 64;   // 32
    for (int kt = 0; kt < NT; kt++) {
        __syncthreads();   // all warps done computing on buf[(kt+1)&1] (tile kt-1)

        if (kt + 1 < NT) {
            int nb = (kt + 1) & 1;
            const float* Kt = Kg + (size_t)(kt + 1) * 64 * HD_;
            const float* Vp = Vg + (size_t)(kt + 1) * 64 * HD_;
            #pragma unroll
            for (int i = 0; i < 8; i++) {
                int row = crow + i * 8;
                cp_async16(k_u32[nb] + (uint32_t)(row * KP + ccol) * 4u, Kt + row * HD_ + ccol);
                cp_async16(v_u32[nb] + (uint32_t)(row * VP + ccol) * 4u, Vp + row * HD_ + ccol);
            }
            CP_COMMIT();
            CP_WAIT(1);    // current tile's group (issued last iter) is done
        } else {
            CP_WAIT(0);
        }
        __syncthreads();   // copies visible to all warps

        const float* Khi = Kb[kt & 1];
        const float* Vt  = Vb[kt & 1];

        // ---- scores (log2 domain): 1 MMA, fragments pure LDS ----
        float Sf[2][8][4];
        #pragma unroll
        for (int mf = 0; mf < 2; mf++)
            #pragma unroll
            for (int nt = 0; nt < 8; nt++)
                #pragma unroll
                for (int j = 0; j < 4; j++) Sf[mf][nt][j] = 0.f;

        #pragma unroll
        for (int kc = 0; kc < 8; kc++) {
            uint32_t ah[2][4];
            #pragma unroll
            for (int mf = 0; mf < 2; mf++) {
                int qi = (wm + mf * 16 + g) * QP + kc * 8 + t;
                ah[mf][0] = __float_as_uint(Qs[qi]);
                ah[mf][1] = __float_as_uint(Qs[qi + 8 * QP]);
                ah[mf][2] = __float_as_uint(Qs[qi + 4]);
                ah[mf][3] = __float_as_uint(Qs[qi + 8 * QP + 4]);
            }
            #pragma unroll
            for (int nt = 0; nt < 8; nt++) {
                int kb = (nt * 8 + g) * KP + kc * 8 + t;
                uint32_t bh0 = __float_as_uint(Khi[kb]);
                uint32_t bh1 = __float_as_uint(Khi[kb + 4]);
                #pragma unroll
                for (int mf = 0; mf < 2; mf++)
                    mma_tf32(Sf[mf][nt], ah[mf][0], ah[mf][1], ah[mf][2], ah[mf][3], bh0, bh1);
            }
        }

        // ---- online softmax (base-2) ----
        #pragma unroll
        for (int mf = 0; mf < 2; mf++) {
            float mx0 = -INFINITY, mx1 = -INFINITY;
            #pragma unroll
            for (int nt = 0; nt < 8; nt++) {
                mx0 = fmaxf(mx0, fmaxf(Sf[mf][nt][0], Sf[mf][nt][1]));
                mx1 = fmaxf(mx1, fmaxf(Sf[mf][nt][2], Sf[mf][nt][3]));
            }
            mx0 = fmaxf(mx0, __shfl_xor_sync(0xffffffffu, mx0, 1));
            mx0 = fmaxf(mx0, __shfl_xor_sync(0xffffffffu, mx0, 2));
            mx1 = fmaxf(mx1, __shfl_xor_sync(0xffffffffu, mx1, 1));
            mx1 = fmaxf(mx1, __shfl_xor_sync(0xffffffffu, mx1, 2));

            float mn0 = fmaxf(m[mf][0], mx0);
            float mn1 = fmaxf(m[mf][1], mx1);
            float alp0 = ex2(m[mf][0] - mn0);
            float alp1 = ex2(m[mf][1] - mn1);

            float ls0 = 0.f, ls1 = 0.f;
            #pragma unroll
            for (int nt = 0; nt < 8; nt++) {
                Sf[mf][nt][0] = ex2(Sf[mf][nt][0] - mn0);
                Sf[mf][nt][1] = ex2(Sf[mf][nt][1] - mn0);
                Sf[mf][nt][2] = ex2(Sf[mf][nt][2] - mn1);
                Sf[mf][nt][3] = ex2(Sf[mf][nt][3] - mn1);
                ls0 += Sf[mf][nt][0] + Sf[mf][nt][1];
                ls1 += Sf[mf][nt][2] + Sf[mf][nt][3];
            }
            ls0 += __shfl_xor_sync(0xffffffffu, ls0, 1);
            ls0 += __shfl_xor_sync(0xffffffffu, ls0, 2);
            ls1 += __shfl_xor_sync(0xffffffffu, ls1, 1);
            ls1 += __shfl_xor_sync(0xffffffffu, ls1, 2);

            l[mf][0] = l[mf][0] * alp0 + ls0;  m[mf][0] = mn0;
            l[mf][1] = l[mf][1] * alp1 + ls1;  m[mf][1] = mn1;

            #pragma unroll
            for (int nt = 0; nt < 8; nt++) {
                O[mf][nt][0] *= alp0;  O[mf][nt][1] *= alp0;
                O[mf][nt][2] *= alp1;  O[mf][nt][3] *= alp1;
            }
        }

        // ---- O += P @ V ----
        const int src0 = (lane & ~3) + (t >> 1);
        const int src2 = src0 + 2;
        const bool odd = (t & 1);

        #pragma unroll
        for (int kc = 0; kc < 8; kc++) {
            uint32_t a[2][4];
            #pragma unroll
            for (int mf = 0; mf < 2; mf++) {
                float e0 = __shfl_sync(0xffffffffu, Sf[mf][kc][0], src0);
                float e1 = __shfl_sync(0xffffffffu, Sf[mf][kc][1], src0);
                float f0 = __shfl_sync(0xffffffffu, Sf[mf][kc][0], src2);
                float f1 = __shfl_sync(0xffffffffu, Sf[mf][kc][1], src2);
                float h0 = __shfl_sync(0xffffffffu, Sf[mf][kc][2], src0);
                float h1 = __shfl_sync(0xffffffffu, Sf[mf][kc][3], src0);
                float i0 = __shfl_sync(0xffffffffu, Sf[mf][kc][2], src2);
                float i1 = __shfl_sync(0xffffffffu, Sf[mf][kc][3], src2);
                a[mf][0] = f2tf(odd ? e1 : e0);
                a[mf][1] = f2tf(odd ? h1 : h0);
                a[mf][2] = f2tf(odd ? f1 : f0);
                a[mf][3] = f2tf(odd ? i1 : i0);
            }
            #pragma unroll
            for (int nt = 0; nt < 8; nt++) {
                int vi = (kc * 8 + t) * VP + nt * 8 + g;
                uint32_t bh0 = __float_as_uint(Vt[vi]);
                uint32_t bh1 = __float_as_uint(Vt[vi + 4 * VP]);
                #pragma unroll
                for (int mf = 0; mf < 2; mf++)
                    mma_tf32(O[mf][nt], a[mf][0], a[mf][1], a[mf][2], a[mf][3], bh0, bh1);
            }
        }
    }

    // ---- epilogue ----
    int b = bh >> 4;
    int h = bh & 15;
    #pragma unroll
    for (int mf = 0; mf < 2; mf++) {
        float inv0 = 1.f / l[mf][0];
        float inv1 = 1.f / l[mf][1];
        int srow = qt * 128 + wm + mf * 16 + g;
        size_t base0 = ((size_t)(b * S_ + srow) * H_ + h) * HD_;
        size_t base1 = base0 + (size_t)8 * H_ * HD_;
        #pragma unroll
        for (int nt = 0; nt < 8; nt++) {
            int col = nt * 8 + 2 * t;
            *(float2*)&out[base0 + col] =
                make_float2(O[mf][nt][0] * inv0, O[mf][nt][1] * inv0);
            *(float2*)&out[base1 + col] =
                make_float2(O[mf][nt][2] * inv1, O[mf][nt][3] * inv1);
        }
    }
}

extern "C" void kernel_launch(void* const* d_in, const int* in_sizes, int n_in,
                              void* d_out, int out_size)
{
    const float* hs = (const float*)d_in[0];
    const float* w  = (const float*)d_in[1];
    const float* qb = (const float*)d_in[2];
    const float* vb = (const float*)d_in[3];
    float* out = (float*)d_out;

    dim3 g1(N3_ / 128, M_ / 128);   // 24 x 32
    qkv_mma_kernel<<<g1, 256>>>(hs, w, qb, vb);

    cudaFuncSetAttribute(attn8_kernel,
                         cudaFuncAttributeMaxDynamicSharedMemorySize, ATTN_SMEM_BYTES);
    dim3 g2(S_ / 128, B_ * H_);     // 16 x 32
    attn8_kernel<<<g2, 128, ATTN_SMEM_BYTES>>>(out);
}